// round 12
// baseline (speedup 1.0000x reference)
#include <cuda_runtime.h>
#include <cuda_fp16.h>
#include <cstdint>
#include <cstddef>

#define DEVFN __device__ __forceinline__
typedef unsigned long long u64t;

// ---------------- static device scratch (no cudaMalloc allowed) -------------
__device__ float g_xproj[16 * 1024 * 1024]; // layer-0 gate pre-activations
__device__ float g_h1[16 * 1024 * 256];     // layer-1 hidden states

// ---------------- helpers ----------------------------------------------------
DEVFN uint32_t smem_u32(const void* p) {
    uint32_t a;
    asm("{ .reg .u64 t; cvta.to.shared.u64 t, %1; cvt.u32.u64 %0, t; }" : "=r"(a) : "l"(p));
    return a;
}
DEVFN float frcp_(float x) { float r; asm("rcp.approx.f32 %0, %1;" : "=f"(r) : "f"(x)); return r; }
DEVFN float fexp2_(float x) { float r; asm("ex2.approx.f32 %0, %1;" : "=f"(r) : "f"(x)); return r; }
DEVFN float sigm_(float x) { return frcp_(1.0f + fexp2_(-1.4426950408889634f * x)); }
DEVFN float tanh_(float x) { return 1.0f - 2.0f * frcp_(1.0f + fexp2_(2.8853900817779268f * x)); }
DEVFN void cluster_sync_() {
    asm volatile("barrier.cluster.arrive.aligned;\n\tbarrier.cluster.wait.aligned;\n" ::: "memory");
}
DEVFN u64t ffma2_(u64t a, u64t b, u64t c) {
    u64t d;
    asm("fma.rn.f32x2 %0, %1, %2, %3;" : "=l"(d) : "l"(a), "l"(b), "l"(c));
    return d;
}
DEVFN float pairsum_(u64t s) {
    return __uint_as_float((uint32_t)s) + __uint_as_float((uint32_t)(s >> 32));
}
DEVFN u64t pack2_(float lo, float hi) {
    u64t r;
    asm("mov.b64 %0, {%1, %2};" : "=l"(r) : "f"(lo), "f"(hi));
    return r;
}
// bit casts half2 <-> u32 (the intrinsics I used before don't exist)
DEVFN uint32_t h2_as_u32_(__half2 h) { uint32_t u; memcpy(&u, &h, 4); return u; }
DEVFN __half2 u32_as_h2_(uint32_t u) { __half2 h; memcpy(&h, &u, 4); return h; }

DEVFN float fold_(float lo, float hi, int mask, int lane) {
    float mine   = (lane & mask) ? hi : lo;
    float theirs = (lane & mask) ? lo : hi;
    return mine + __shfl_xor_sync(0xffffffffu, theirs, mask);
}
DEVFN uint32_t mapa_(uint32_t addr, uint32_t peer) {
    uint32_t r;
    asm("mapa.shared::cluster.u32 %0, %1, %2;" : "=r"(r) : "r"(addr), "r"(peer));
    return r;
}
DEVFN void mbar_init_(uint32_t a, uint32_t cnt) {
    asm volatile("mbarrier.init.shared.b64 [%0], %1;" :: "r"(a), "r"(cnt) : "memory");
}
DEVFN void mbar_expect_(uint32_t a, uint32_t bytes) {
    asm volatile("mbarrier.arrive.expect_tx.shared.b64 _, [%0], %1;" :: "r"(a), "r"(bytes) : "memory");
}
DEVFN void mbar_wait_(uint32_t a, uint32_t par) {
    asm volatile(
        "{\n\t.reg .pred P;\n\t"
        "W%=:\n\t"
        "mbarrier.try_wait.parity.acquire.cta.shared::cta.b64 P, [%0], %1, 0x989680;\n\t"
        "@!P bra W%=;\n\t}"
        :: "r"(a), "r"(par) : "memory");
}
DEVFN void st_async_u64_(uint32_t raddr, u64t v, uint32_t rmbar) {
    asm volatile(
        "st.async.shared::cluster.mbarrier::complete_tx::bytes.b64 [%0], %1, [%2];"
        :: "r"(raddr), "l"(v), "r"(rmbar) : "memory");
}

// ============================================================================
// GEMM for layer-0 x-projection (K=32): C = A@B^T + bias1 + bias2
// ============================================================================
__global__ void __launch_bounds__(256, 4)
gemm_xproj(const float* __restrict__ A, const float* __restrict__ B,
           const float* __restrict__ bias1, const float* __restrict__ bias2,
           float* __restrict__ C, int K)
{
    __shared__ __align__(16) float As[32][68];
    __shared__ __align__(16) float Bs[32][68];

    const int tid = threadIdx.x;
    const int tx = tid & 15, ty = tid >> 4;
    const int m0 = blockIdx.y * 64, n0 = blockIdx.x * 64;
    const int lr = tid >> 2;
    const int lcb = (tid & 3) * 4;

    float acc[4][4] = {};

    for (int kk = 0; kk < K; kk += 32) {
#pragma unroll
        for (int it = 0; it < 2; it++) {
            int k0 = lcb + it * 16;
            float4 a = *(const float4*)(A + (size_t)(m0 + lr) * K + kk + k0);
            As[k0 + 0][lr] = a.x; As[k0 + 1][lr] = a.y;
            As[k0 + 2][lr] = a.z; As[k0 + 3][lr] = a.w;
            float4 bb = *(const float4*)(B + (size_t)(n0 + lr) * K + kk + k0);
            Bs[k0 + 0][lr] = bb.x; Bs[k0 + 1][lr] = bb.y;
            Bs[k0 + 2][lr] = bb.z; Bs[k0 + 3][lr] = bb.w;
        }
        __syncthreads();
#pragma unroll
        for (int k = 0; k < 32; k++) {
            float4 av = *(const float4*)&As[k][ty * 4];
            float4 bv = *(const float4*)&Bs[k][tx * 4];
            float am[4] = {av.x, av.y, av.z, av.w};
            float bn[4] = {bv.x, bv.y, bv.z, bv.w};
#pragma unroll
            for (int i = 0; i < 4; i++)
#pragma unroll
                for (int jn = 0; jn < 4; jn++)
                    acc[i][jn] = fmaf(am[i], bn[jn], acc[i][jn]);
        }
        __syncthreads();
    }
    float4 b1 = *(const float4*)(bias1 + n0 + tx * 4);
    float4 b2 = *(const float4*)(bias2 + n0 + tx * 4);
    float bad[4] = {b1.x + b2.x, b1.y + b2.y, b1.z + b2.z, b1.w + b2.w};
#pragma unroll
    for (int i = 0; i < 4; i++) {
        float4 o;
        o.x = acc[i][0] + bad[0]; o.y = acc[i][1] + bad[1];
        o.z = acc[i][2] + bad[2]; o.w = acc[i][3] + bad[3];
        *(float4*)(C + (size_t)(m0 + ty * 4 + i) * 1024 + n0 + tx * 4) = o;
    }
}

// ============================================================================
// FUSED 2-layer LSTM, 1-step skew. 8-CTA cluster per batch; 128 CTAs x 512 thr.
// Iteration t (0..1024): compute h0[t] (layer 0) and h1[t-1] (layer 1); both
// depend only on the PREVIOUS broadcast {h0[t-1], h1[t-2]}. 1025 rounds total
// instead of 2048, and the x_proj1 GEMM folds into the loop.
// Warp w owns rows {2w, 2w+1} of its CTA's 32-slice for BOTH layers.
//   W_hh0: registers (64 f/thread).  W_hh1: fp32 SMEM [chunk][tid] (128KB).
//   W_ih1: fp16 SMEM [chunk][tid] (64KB), expanded to fp32 before ffma2.
// Per step per warp: R8's L0 block + L1 accumulation + two 9-shfl folding
// butterflies; lanes 0/4 do activations; lane 0 sends pk0 (h0 pair) + pk1
// (h1 pair) via st.async.b64 to 8 peers (tx 2048 B/dest/step).
// Dual-parity mbarriers (slack-2); no __syncthreads in loop.
// ============================================================================
#define FUSED_SMEM_BYTES 201248
// offsets: whh1 @0 (131072 B), wih1 @131072 (65536 B), h0buf @196608 (2304 B),
//          h1buf @198912 (2304 B), mbar @201216 (16 B)

__global__ void __cluster_dims__(8, 1, 1) __launch_bounds__(512, 1)
lstm_fused(const float* __restrict__ Whh0g, const float* __restrict__ Whh1g,
           const float* __restrict__ Wih1g,
           const float* __restrict__ bih1, const float* __restrict__ bhh1,
           const float* __restrict__ xproj, float* __restrict__ hout1)
{
    extern __shared__ __align__(16) char smem[];
    char*  whh1  = smem;
    char*  wih1  = smem + 131072;
    float* h0buf = (float*)(smem + 196608);   // [2][288], stride-36 groups
    float* h1buf = (float*)(smem + 198912);   // [2][288]

    const int tid  = threadIdx.x;
    const int lane = tid & 31;
    const int w    = tid >> 5;
    uint32_t rank;
    asm("mov.u32 %0, %%cluster_ctarank;" : "=r"(rank));
    const int b = blockIdx.x >> 3;
    const int base = (int)rank * 32;

    // ---- W_hh0 in registers (R8 layout): [row][gate][chunk] -----------------
    ulonglong2 W[2][4][2];
#pragma unroll
    for (int r = 0; r < 2; r++)
#pragma unroll
        for (int g = 0; g < 4; g++) {
            const float* row = Whh0g + (size_t)(g * 256 + base + 2 * w + r) * 256 + 8 * lane;
            W[r][g][0] = *(const ulonglong2*)(row);
            W[r][g][1] = *(const ulonglong2*)(row + 4);
        }

    // ---- stage W_hh1 (fp32) and W_ih1 (fp16) into SMEM ----------------------
#pragma unroll
    for (int cch = 0; cch < 16; cch++) {   // hh chunk: r=c>>3, g=(c>>1)&3, half=c&1
        int r = cch >> 3, g = (cch >> 1) & 3, hh = cch & 1;
        float4 wv = *(const float4*)(Whh1g + (size_t)(g * 256 + base + 2 * w + r) * 256
                                     + 8 * lane + 4 * hh);
        *(float4*)(whh1 + cch * 8192 + tid * 16) = wv;
    }
#pragma unroll
    for (int cch = 0; cch < 8; cch++) {    // ih chunk: r=c>>2, g=c&3
        int r = cch >> 2, g = cch & 3;
        const float* src = Wih1g + (size_t)(g * 256 + base + 2 * w + r) * 256 + 8 * lane;
        float4 a = *(const float4*)(src);
        float4 c4 = *(const float4*)(src + 4);
        uint4 pk;
        pk.x = h2_as_u32_(__floats2half2_rn(a.x, a.y));
        pk.y = h2_as_u32_(__floats2half2_rn(a.z, a.w));
        pk.z = h2_as_u32_(__floats2half2_rn(c4.x, c4.y));
        pk.w = h2_as_u32_(__floats2half2_rn(c4.z, c4.w));
        *(uint4*)(wih1 + cch * 8192 + tid * 16) = pk;
    }

    // zero both phases of both h buffers (1152 floats, contiguous)
    for (int i = tid; i < 1152; i += 512) h0buf[i] = 0.0f;

    const uint32_t mb0 = smem_u32(smem + 201216);            // mb1 = mb0 + 8
    const uint32_t h0b = smem_u32(h0buf);
    if (tid == 0) { mbar_init_(mb0, 1); mbar_init_(mb0 + 8, 1); }
    __syncthreads();
    cluster_sync_();

    const bool prod = (lane & 0x1B) == 0;     // lanes 0 and 4
    const int jm = 2 * w + ((lane >> 2) & 1); // producer's row within CTA slice
    const float* xr = xproj + (size_t)b * 1024 * 1024 + base + jm;

    // producer-lane L1 biases (b_ih1 + b_hh1 per gate for row jm)
    float bs0 = 0.f, bs1 = 0.f, bs2 = 0.f, bs3 = 0.f;
    if (prod) {
        int rowg = base + jm;
        bs0 = bih1[rowg] + bhh1[rowg];
        bs1 = bih1[256 + rowg] + bhh1[256 + rowg];
        bs2 = bih1[512 + rowg] + bhh1[512 + rowg];
        bs3 = bih1[768 + rowg] + bhh1[768 + rowg];
    }

    uint32_t rdst[8], rmb[8];                 // h1 slot = h0 slot + 2304
    if (lane == 0) {
        uint32_t slot = h0b + (uint32_t)((int)rank * 144 + 8 * w);
#pragma unroll
        for (int r = 0; r < 8; r++) {
            rdst[r] = mapa_(slot, (uint32_t)r);
            rmb[r]  = mapa_(mb0, (uint32_t)r);
        }
    }

    const uint32_t hoff = (uint32_t)((lane >> 2) * 36 + 8 * (lane & 3));

    float c0 = 0.0f, c1 = 0.0f;
    float xn0 = 0.f, xn1 = 0.f, xn2 = 0.f, xn3 = 0.f;
    if (prod) { xn0 = xr[0]; xn1 = xr[256]; xn2 = xr[512]; xn3 = xr[768]; }

#pragma unroll 1
    for (int t = 0; t <= 1024; t++) {
        float xc0 = xn0, xc1 = xn1, xc2 = xn2, xc3 = xn3;
        if (prod && t < 1023) {
            const float* x2 = xr + (size_t)(t + 1) * 1024;
            xn0 = x2[0]; xn1 = x2[256]; xn2 = x2[512]; xn3 = x2[768];
        }
        if (t > 0) mbar_wait_(mb0 + ((t & 1) ? 0u : 8u), (uint32_t)(((t - 1) >> 1) & 1));
        if (tid == 0 && t < 1024) mbar_expect_(mb0 + ((t & 1) ? 8u : 0u), 2048);

        const float* hp0 = h0buf + (t & 1) * 288 + hoff;
        ulonglong2 A0 = *(const ulonglong2*)(hp0);
        ulonglong2 A1 = *(const ulonglong2*)(hp0 + 4);
        const float* hp1 = h1buf + (t & 1) * 288 + hoff;
        ulonglong2 B0 = *(const ulonglong2*)(hp1);
        ulonglong2 B1 = *(const ulonglong2*)(hp1 + 4);

        // ---------------- layer 0 (W in regs) -------------------------------
        float v[8];
#pragma unroll
        for (int r = 0; r < 2; r++)
#pragma unroll
            for (int g = 0; g < 4; g++) {
                u64t a = ffma2_(W[r][g][0].x, A0.x, 0ULL);
                a = ffma2_(W[r][g][0].y, A0.y, a);
                a = ffma2_(W[r][g][1].x, A1.x, a);
                a = ffma2_(W[r][g][1].y, A1.y, a);
                v[r * 4 + g] = pairsum_(a);
            }
        {
            float u0 = fold_(v[0], v[1], 1, lane);
            float u1 = fold_(v[2], v[3], 1, lane);
            float u2 = fold_(v[4], v[5], 1, lane);
            float u3 = fold_(v[6], v[7], 1, lane);
            float w0 = fold_(u0, u1, 2, lane);
            float w1 = fold_(u2, u3, 2, lane);
            float z  = fold_(w0, w1, 4, lane);
            z += __shfl_xor_sync(0xffffffffu, z, 8);
            z += __shfl_xor_sync(0xffffffffu, z, 16);
            float z1 = __shfl_down_sync(0xffffffffu, z, 1);
            float z2 = __shfl_down_sync(0xffffffffu, z, 2);
            float z3 = __shfl_down_sync(0xffffffffu, z, 3);
            v[0] = z; v[1] = z1; v[2] = z2; v[3] = z3;
        }
        float hval0 = 0.0f;
        if (prod) {
            float iv = sigm_(v[0] + xc0);
            float fv = sigm_(v[1] + xc1);
            float gg = tanh_(v[2] + xc2);
            float ov = sigm_(v[3] + xc3);
            c0 = fmaf(fv, c0, iv * gg);
            hval0 = ov * tanh_(c0);
        }
        float hhi0 = __shfl_sync(0xffffffffu, hval0, 4);

        // ---------------- layer 1 (W_hh1 fp32 SMEM + W_ih1 fp16 SMEM) -------
        u64t a2[8] = {0ULL, 0ULL, 0ULL, 0ULL, 0ULL, 0ULL, 0ULL, 0ULL};
#pragma unroll
        for (int cch = 0; cch < 16; cch++) {
            ulonglong2 wv = *(const ulonglong2*)(whh1 + cch * 8192 + tid * 16);
            const int unit = (cch >> 3) * 4 + ((cch >> 1) & 3);
            if (cch & 1) {
                a2[unit] = ffma2_(wv.x, B1.x, a2[unit]);
                a2[unit] = ffma2_(wv.y, B1.y, a2[unit]);
            } else {
                a2[unit] = ffma2_(wv.x, B0.x, a2[unit]);
                a2[unit] = ffma2_(wv.y, B0.y, a2[unit]);
            }
        }
#pragma unroll
        for (int cch = 0; cch < 8; cch++) {
            uint4 iw = *(const uint4*)(wih1 + cch * 8192 + tid * 16);
            const int unit = (cch >> 2) * 4 + (cch & 3);
            float2 f0 = __half22float2(u32_as_h2_(iw.x));
            float2 f1 = __half22float2(u32_as_h2_(iw.y));
            float2 f2 = __half22float2(u32_as_h2_(iw.z));
            float2 f3 = __half22float2(u32_as_h2_(iw.w));
            a2[unit] = ffma2_(pack2_(f0.x, f0.y), A0.x, a2[unit]);
            a2[unit] = ffma2_(pack2_(f1.x, f1.y), A0.y, a2[unit]);
            a2[unit] = ffma2_(pack2_(f2.x, f2.y), A1.x, a2[unit]);
            a2[unit] = ffma2_(pack2_(f3.x, f3.y), A1.y, a2[unit]);
        }
        float v1[8];
#pragma unroll
        for (int k = 0; k < 8; k++) v1[k] = pairsum_(a2[k]);
        {
            float u0 = fold_(v1[0], v1[1], 1, lane);
            float u1 = fold_(v1[2], v1[3], 1, lane);
            float u2 = fold_(v1[4], v1[5], 1, lane);
            float u3 = fold_(v1[6], v1[7], 1, lane);
            float w0 = fold_(u0, u1, 2, lane);
            float w1 = fold_(u2, u3, 2, lane);
            float z  = fold_(w0, w1, 4, lane);
            z += __shfl_xor_sync(0xffffffffu, z, 8);
            z += __shfl_xor_sync(0xffffffffu, z, 16);
            float z1 = __shfl_down_sync(0xffffffffu, z, 1);
            float z2 = __shfl_down_sync(0xffffffffu, z, 2);
            float z3 = __shfl_down_sync(0xffffffffu, z, 3);
            v1[0] = z; v1[1] = z1; v1[2] = z2; v1[3] = z3;
        }
        float hval1 = 0.0f;
        if (prod && t > 0) {          // t==0: h1[-1] := 0, c1 untouched
            float iv = sigm_(v1[0] + bs0);
            float fv = sigm_(v1[1] + bs1);
            float gg = tanh_(v1[2] + bs2);
            float ov = sigm_(v1[3] + bs3);
            c1 = fmaf(fv, c1, iv * gg);
            hval1 = ov * tanh_(c1);
        }
        float hhi1 = __shfl_sync(0xffffffffu, hval1, 4);

        // ---------------- sends + stores -------------------------------------
        if (lane == 0) {
            u64t pk0 = (u64t)__float_as_uint(hval0) | ((u64t)__float_as_uint(hhi0) << 32);
            u64t pk1 = (u64t)__float_as_uint(hval1) | ((u64t)__float_as_uint(hhi1) << 32);
            if (t < 1024) {
                uint32_t boff = (uint32_t)(((t + 1) & 1) * 1152);
                uint32_t msel = (t & 1) ? 8u : 0u;
#pragma unroll
                for (int rr = 0; rr < 8; rr++) {
                    st_async_u64_(rdst[rr] + boff, pk0, rmb[rr] + msel);
                    st_async_u64_(rdst[rr] + 2304u + boff, pk1, rmb[rr] + msel);
                }
            }
            if (t >= 1)
                *(u64t*)(hout1 + (size_t)(b * 1024 + (t - 1)) * 256 + base + 2 * w) = pk1;
        }
    }
    cluster_sync_();
}

// ============================================================================
// Attention (last timestep only, algebraically reduced) + output heads.
// ============================================================================
#define ATTN_SMEM_FLOATS 17416
#define ATTN_SMEM_BYTES (ATTN_SMEM_FLOATS * 4)

__global__ void __launch_bounds__(256, 1)
attn_kernel(const float* __restrict__ h1all,
            const float* __restrict__ Wq, const float* __restrict__ bq,
            const float* __restrict__ Wk, const float* __restrict__ bk,
            const float* __restrict__ Wv, const float* __restrict__ bv,
            const float* __restrict__ Wo, const float* __restrict__ bo,
            const float* __restrict__ Wm, const float* __restrict__ bm,
            const float* __restrict__ Wvar, const float* __restrict__ bvar,
            float* __restrict__ out)
{
    extern __shared__ float sm[];
    float* tile   = sm;
    float* scores = sm + 4096;
    float* u      = sm + 12288;
    float* hb     = sm + 14336;
    float* qv     = sm + 16384;
    float* h2last = sm + 16640;
    float* attnv  = sm + 16896;
    float* ctx    = sm + 17152;
    float* qb     = sm + 17408;

    const int b = blockIdx.x;
    const int tid = threadIdx.x;
    const int w = tid >> 5, lane = tid & 31;
    const float* hbase = h1all + (size_t)b * 1024 * 256;

    h2last[tid] = hbase[1023 * 256 + tid];
    __syncthreads();

    {
        float acc = bq[tid];
        const float* wr = Wq + (size_t)tid * 256;
#pragma unroll 8
        for (int d = 0; d < 256; d++) acc = fmaf(wr[d], h2last[d], acc);
        qv[tid] = acc;
    }
    __syncthreads();

#pragma unroll 1
    for (int i = 0; i < 8; i++) {
        int flat = tid + (i << 8);
        int hh = flat >> 8, d = flat & 255;
        float acc = 0.0f;
        const float* basep = Wk + (size_t)hh * 32 * 256 + d;
#pragma unroll
        for (int e = 0; e < 32; e++) acc = fmaf(basep[(size_t)e * 256], qv[(hh << 5) + e], acc);
        u[hh * 256 + d] = acc;
    }
    if (tid < 8) {
        float a = 0.0f;
        for (int e = 0; e < 32; e++) a = fmaf(qv[tid * 32 + e], bk[tid * 32 + e], a);
        qb[tid] = a;
    }
    __syncthreads();

    const float scale = 0.17677669529663687f;
    const float L2D   = -0.07400058144377693f;
    const float LOG2E = 1.4426950408889634f;
    float mmax = -1e30f;

#pragma unroll 1
    for (int tt = 0; tt < 64; tt++) {
        {
            int tl = tid >> 4, d0 = (tid & 15) * 16;
            const float4* src = (const float4*)(hbase + (size_t)(tt * 16 + tl) * 256 + d0);
            float4* dst = (float4*)(tile + tl * 256 + d0);
            dst[0] = src[0]; dst[1] = src[1]; dst[2] = src[2]; dst[3] = src[3];
        }
        __syncthreads();
#pragma unroll 1
        for (int tl = 0; tl < 16; tl++) {
            int t = tt * 16 + tl;
            float part = 0.0f;
            const float* tr = tile + tl * 256 + lane * 8;
            const float* ur = u + w * 256 + lane * 8;
#pragma unroll
            for (int i = 0; i < 8; i++) part = fmaf(ur[i], tr[i], part);
#pragma unroll
            for (int m = 16; m > 0; m >>= 1) part += __shfl_xor_sync(0xffffffffu, part, m);
            float s = (part + qb[w]) * scale * fexp2_((float)(1023 - t) * L2D);
            if (lane == 0) scores[w * 1024 + t] = s;
            mmax = fmaxf(mmax, s);
        }
        __syncthreads();
    }

    float Z = 0.0f;
    for (int t = lane; t < 1024; t += 32) Z += fexp2_(LOG2E * (scores[w * 1024 + t] - mmax));
#pragma unroll
    for (int m = 16; m > 0; m >>= 1) Z += __shfl_xor_sync(0xffffffffu, Z, m);
    float invZ = 1.0f / Z;

    float hbar[8] = {0, 0, 0, 0, 0, 0, 0, 0};
#pragma unroll 1
    for (int tt = 0; tt < 64; tt++) {
        {
            int tl = tid >> 4, d0 = (tid & 15) * 16;
            const float4* src = (const float4*)(hbase + (size_t)(tt * 16 + tl) * 256 + d0);
            float4* dst = (float4*)(tile + tl * 256 + d0);
            dst[0] = src[0]; dst[1] = src[1]; dst[2] = src[2]; dst[3] = src[3];
        }
        __syncthreads();
#pragma unroll 1
        for (int tl = 0; tl < 16; tl++) {
            int t = tt * 16 + tl;
            float pr = fexp2_(LOG2E * (scores[w * 1024 + t] - mmax)) * invZ;
            const float* tr = tile + tl * 256 + lane * 8;
#pragma unroll
            for (int i = 0; i < 8; i++) hbar[i] = fmaf(pr, tr[i], hbar[i]);
        }
        __syncthreads();
    }
#pragma unroll
    for (int i = 0; i < 8; i++) hb[w * 256 + lane * 8 + i] = hbar[i];
    __syncthreads();

    {
        int hh = tid >> 5;
        float acc = bv[tid];
        const float* wr = Wv + (size_t)tid * 256;
        const float* hr = hb + hh * 256;
#pragma unroll 8
        for (int d = 0; d < 256; d++) acc = fmaf(wr[d], hr[d], acc);
        attnv[tid] = acc;
    }
    __syncthreads();
    {
        float acc = bo[tid];
        const float* wr = Wo + (size_t)tid * 256;
#pragma unroll 8
        for (int d = 0; d < 256; d++) acc = fmaf(wr[d], attnv[d], acc);
        ctx[tid] = acc;
    }
    __syncthreads();
    if (tid < 5) {
        float acc = bm[tid];
        const float* wr = Wm + (size_t)tid * 256;
#pragma unroll 8
        for (int d = 0; d < 256; d++) acc = fmaf(wr[d], ctx[d], acc);
        out[b * 5 + tid] = acc;
    } else if (tid >= 32 && tid < 37) {
        int jj = tid - 32;
        float acc = bvar[jj];
        const float* wr = Wvar + (size_t)jj * 256;
#pragma unroll 8
        for (int d = 0; d < 256; d++) acc = fmaf(wr[d], ctx[d], acc);
        out[80 + b * 5 + jj] = acc;
    }
}

// ============================================================================
extern "C" void kernel_launch(void* const* d_in, const int* in_sizes, int n_in,
                              void* d_out, int out_size)
{
    (void)in_sizes; (void)n_in; (void)out_size;
    const float* x    = (const float*)d_in[0];
    const float* Wih0 = (const float*)d_in[1];
    const float* Whh0 = (const float*)d_in[2];
    const float* bih0 = (const float*)d_in[3];
    const float* bhh0 = (const float*)d_in[4];
    const float* Wih1 = (const float*)d_in[5];
    const float* Whh1 = (const float*)d_in[6];
    const float* bih1 = (const float*)d_in[7];
    const float* bhh1 = (const float*)d_in[8];
    const float* Wq   = (const float*)d_in[9];
    const float* bq   = (const float*)d_in[10];
    const float* Wk   = (const float*)d_in[11];
    const float* bk   = (const float*)d_in[12];
    const float* Wv   = (const float*)d_in[13];
    const float* bv   = (const float*)d_in[14];
    const float* Wo   = (const float*)d_in[15];
    const float* bo   = (const float*)d_in[16];
    const float* Wm   = (const float*)d_in[17];
    const float* bm   = (const float*)d_in[18];
    const float* Wvar = (const float*)d_in[19];
    const float* bvar = (const float*)d_in[20];
    float* out = (float*)d_out;

    float *xp, *h1p;
    cudaGetSymbolAddress((void**)&xp,  g_xproj);
    cudaGetSymbolAddress((void**)&h1p, g_h1);
    cudaFuncSetAttribute(attn_kernel, cudaFuncAttributeMaxDynamicSharedMemorySize, ATTN_SMEM_BYTES);
    cudaFuncSetAttribute(lstm_fused, cudaFuncAttributeMaxDynamicSharedMemorySize, FUSED_SMEM_BYTES);

    gemm_xproj<<<dim3(16, 256), 256>>>(x, Wih0, bih0, bhh0, xp, 32);
    lstm_fused<<<128, 512, FUSED_SMEM_BYTES>>>(Whh0, Whh1, Wih1, bih1, bhh1, xp, h1p);
    attn_kernel<<<16, 256, ATTN_SMEM_BYTES>>>(h1p, Wq, bq, Wk, bk, Wv, bv, Wo, bo,
                                              Wm, bm, Wvar, bvar, out);
}